// round 6
// baseline (speedup 1.0000x reference)
#include <cuda_runtime.h>

#define NB 64
#define NP 8732
#define NC 81
#define NO 16
#define NCHUNK 8
#define CHUNK 1092        // ceil(8732/8)
#define TILE 32           // rows of conf per block in k_main (multiple of 4!)
#define NTILE 273         // ceil(8732/32)

// ---------------- scratch (device globals; no allocation) ----------------
__device__ float              g_bto[NB * NP];        // best truth overlap per prior
__device__ unsigned char      g_bti[NB * NP];        // best truth idx per prior
__device__ unsigned long long g_bpkey[NB * NO];      // packed (iou_bits<<32)|(~p) argmax keys
__device__ float              g_ceneg[NB * NP];      // positive-zeroed CE
__device__ float              g_lossl[NB];
__device__ int                g_npos[NB];
__device__ float              g_cepos[NB];
__device__ float              g_topk[NB];
__device__ int                g_ticket;

// ---------------- K0: zero the cross-kernel accumulators ----------------
__global__ void k_init() {
    int t = threadIdx.x;               // 1024 threads, 1 block
    if (t < NB * NO) g_bpkey[t] = 0ull;
    if (t < NB) { g_lossl[t] = 0.f; g_npos[t] = 0; g_cepos[t] = 0.f; }
    if (t == 0) g_ticket = 0;
}

// ---------------- K1: IoU matching (bit-exact vs reference) ----------------
// grid (NCHUNK, NB), 256 threads
__global__ __launch_bounds__(256) void k_iou(const float* __restrict__ dbox,
                                             const float* __restrict__ truths) {
    int b = blockIdx.y;
    int chunk = blockIdx.x;
    int tid = threadIdx.x;

    __shared__ float sh_t[NO][4];
    __shared__ float sh_area[NO];
    if (tid < NO) {
        float x0 = truths[(b * NO + tid) * 4 + 0];
        float y0 = truths[(b * NO + tid) * 4 + 1];
        float x1 = truths[(b * NO + tid) * 4 + 2];
        float y1 = truths[(b * NO + tid) * 4 + 3];
        sh_t[tid][0] = x0; sh_t[tid][1] = y0; sh_t[tid][2] = x1; sh_t[tid][3] = y1;
        sh_area[tid] = __fmul_rn(__fsub_rn(x1, x0), __fsub_rn(y1, y0));
    }
    __syncthreads();

    float bv[NO];
    int   bp_[NO];
#pragma unroll
    for (int o = 0; o < NO; o++) { bv[o] = -1.f; bp_[o] = 0; }

    int p0 = chunk * CHUNK;
    int p1 = p0 + CHUNK; if (p1 > NP) p1 = NP;

    for (int p = p0 + tid; p < p1; p += 256) {
        float4 db = reinterpret_cast<const float4*>(dbox)[p];
        float px0 = __fsub_rn(db.x, __fmul_rn(db.z, 0.5f));
        float py0 = __fsub_rn(db.y, __fmul_rn(db.w, 0.5f));
        float px1 = __fadd_rn(db.x, __fmul_rn(db.z, 0.5f));
        float py1 = __fadd_rn(db.y, __fmul_rn(db.w, 0.5f));
        float areab = __fmul_rn(__fsub_rn(px1, px0), __fsub_rn(py1, py0));

        float best = -1.f; int bi = 0;
#pragma unroll
        for (int o = 0; o < NO; o++) {
            float ix0 = fmaxf(px0, sh_t[o][0]);
            float iy0 = fmaxf(py0, sh_t[o][1]);
            float ix1 = fminf(px1, sh_t[o][2]);
            float iy1 = fminf(py1, sh_t[o][3]);
            float iw = fmaxf(__fsub_rn(ix1, ix0), 0.f);
            float ih = fmaxf(__fsub_rn(iy1, iy0), 0.f);
            float inter = __fmul_rn(iw, ih);
            float denom = __fsub_rn(__fadd_rn(sh_area[o], areab), inter);
            float iou = __fdiv_rn(inter, denom);
            if (iou > best) { best = iou; bi = o; }        // first-occurrence over o
            if (iou > bv[o]) { bv[o] = iou; bp_[o] = p; }  // first-occurrence over p
        }
        g_bto[b * NP + p] = best;
        g_bti[b * NP + p] = (unsigned char)bi;
    }

    // per-truth argmax over priors: pack (iou_bits << 32) | (~p)
#pragma unroll
    for (int o = 0; o < NO; o++) {
        unsigned long long kk =
            (((unsigned long long)__float_as_uint(bv[o] < 0.f ? 0.f : bv[o])) << 32) |
            (unsigned long long)(0xFFFFFFFFu - (unsigned)bp_[o]);
#pragma unroll
        for (int s = 16; s > 0; s >>= 1) {
            unsigned long long other = __shfl_down_sync(0xFFFFFFFFu, kk, s);
            if (other > kk) kk = other;
        }
        if ((tid & 31) == 0) atomicMax(&g_bpkey[b * NO + o], kk);
    }
}

// ---------------- K2: fused conf_t assignment + loc loss + cross entropy ----------------
// grid (NTILE, NB), 256 threads. Block stages 32 conf rows via coalesced float4,
// each warp reduces 4 rows from smem; lane 0 does matching/encode/CE bookkeeping.
__global__ __launch_bounds__(256) void k_main(const float* __restrict__ conf,
                                              const float* __restrict__ dbox,
                                              const float* __restrict__ truths,
                                              const int* __restrict__ labels,
                                              const float* __restrict__ loc_data) {
    int b = blockIdx.y;
    int r0 = blockIdx.x * TILE;
    int rows = NP - r0; if (rows > TILE) rows = TILE;     // always multiple of 4 (28 on last)
    int tid = threadIdx.x;
    int lane = tid & 31, w = tid >> 5;

    __shared__ float s_conf[TILE * NC];   // 10368 B
    __shared__ float sh_t[NO][4];
    __shared__ int   sh_lab[NO];
    __shared__ int   sh_bp[NO];
    __shared__ float s_ls[8];
    __shared__ int   s_np[8];
    __shared__ float s_ce[8];

    if (tid < NO) {
        sh_t[tid][0] = truths[(b * NO + tid) * 4 + 0];
        sh_t[tid][1] = truths[(b * NO + tid) * 4 + 1];
        sh_t[tid][2] = truths[(b * NO + tid) * 4 + 2];
        sh_t[tid][3] = truths[(b * NO + tid) * 4 + 3];
        sh_lab[tid] = labels[b * NO + tid];
        sh_bp[tid]  = (int)(0xFFFFFFFFu - (unsigned)(g_bpkey[b * NO + tid] & 0xFFFFFFFFull));
    }

    // coalesced float4 staging: base byte offset (b*NP + r0)*324 ≡ 0 mod 16 (r0 % 4 == 0)
    const float4* gsrc = reinterpret_cast<const float4*>(conf + ((size_t)b * NP + r0) * NC);
    float4* sdst = reinterpret_cast<float4*>(s_conf);
    int nf4 = rows * NC / 4;
    for (int i = tid; i < nf4; i += 256) sdst[i] = gsrc[i];
    __syncthreads();

    float lsum = 0.f; int np = 0; float cpos = 0.f;

#pragma unroll
    for (int j = 0; j < 4; j++) {
        int r = w + j * 8;                       // warp's j-th row within tile
        if (r < rows) {
            const float* row = s_conf + r * NC;
            float e = __expf(row[lane]) + __expf(row[lane + 32]);
            if (lane < NC - 64) e += __expf(row[lane + 64]);
#pragma unroll
            for (int s = 16; s > 0; s >>= 1) e += __shfl_xor_sync(0xFFFFFFFFu, e, s);

            if (lane == 0) {
                int p = r0 + r;
                int mo = -1;
#pragma unroll
                for (int o = 0; o < NO; o++)
                    if (sh_bp[o] == p) mo = o;   // ascending o -> last write wins
                float ov; int ti;
                if (mo >= 0) { ov = 2.f; ti = mo; }
                else         { ov = g_bto[b * NP + p]; ti = (int)g_bti[b * NP + p]; }
                int c = (ov < 0.5f) ? 0 : (sh_lab[ti] + 1);
                float ce = __logf(e) - row[c];
                if (c > 0) {
                    np++;
                    cpos += ce;
                    g_ceneg[b * NP + p] = 0.f;
                    float4 db = reinterpret_cast<const float4*>(dbox)[p];
                    float x0 = sh_t[ti][0], y0 = sh_t[ti][1], x1 = sh_t[ti][2], y1 = sh_t[ti][3];
                    float gx = ((x0 + x1) * 0.5f - db.x) / (0.1f * db.z);
                    float gy = ((y0 + y1) * 0.5f - db.y) / (0.1f * db.w);
                    float gw = logf((x1 - x0) / db.z) / 0.2f;
                    float gh = logf((y1 - y0) / db.w) / 0.2f;
                    float4 ld = reinterpret_cast<const float4*>(loc_data)[b * NP + p];
                    float tgt[4] = {gx, gy, gw, gh};
                    float lv[4] = {ld.x, ld.y, ld.z, ld.w};
#pragma unroll
                    for (int q = 0; q < 4; q++) {
                        float d = fabsf(lv[q] - tgt[q]);
                        lsum += (d < 1.f) ? 0.5f * d * d : d - 0.5f;
                    }
                } else {
                    g_ceneg[b * NP + p] = ce;
                }
            }
        }
    }

    // per-block reduce of the lane-0 accumulators (one value per warp)
    if (lane == 0) { s_ls[w] = lsum; s_np[w] = np; s_ce[w] = cpos; }
    __syncthreads();
    if (tid == 0) {
        float L = 0.f, Cp = 0.f; int N = 0;
#pragma unroll
        for (int i = 0; i < 8; i++) { L += s_ls[i]; N += s_np[i]; Cp += s_ce[i]; }
        if (N != 0) {
            atomicAdd(&g_lossl[b], L);
            atomicAdd(&g_npos[b], N);
            atomicAdd(&g_cepos[b], Cp);
        }
    }
}

// ---------------- K3: per-batch top-k sum via radix select + fused finalize ----------------
// grid (NB), 1024 threads
__global__ __launch_bounds__(1024) void k_topk(float* __restrict__ out) {
    int b = blockIdx.x, tid = threadIdx.x;
    int lane = tid & 31;
    const float* vals = g_ceneg + b * NP;
    int k = g_npos[b] * 3;
    if (k > NP) k = NP;

    __shared__ int hist[256];
    __shared__ unsigned s_prefix;
    __shared__ int s_krem;
    float topk = 0.f;

    if (k > 0) {
        if (tid == 0) { s_prefix = 0u; s_krem = k; }
        __syncthreads();

        for (int pass = 0; pass < 4; pass++) {
            int shift = 24 - pass * 8;
            if (tid < 256) hist[tid] = 0;
            __syncthreads();
            unsigned prefix = s_prefix;
            unsigned himask = (pass == 0) ? 0u : (0xFFFFFFFFu << (shift + 8));
            for (int base = 0; base < NP; base += 1024) {
                int p = base + tid;
                int bin = -1;
                if (p < NP) {
                    unsigned u = __float_as_uint(vals[p]);
                    if ((u & himask) == prefix) bin = (int)((u >> shift) & 0xFF);
                }
                unsigned mm = __match_any_sync(0xFFFFFFFFu, bin);
                if (bin >= 0 && lane == __ffs(mm) - 1)
                    atomicAdd(&hist[bin], __popc(mm));
            }
            __syncthreads();
            if (tid == 0) {
                int krem = s_krem, cum = 0, bin;
                for (bin = 255; bin > 0; bin--) {
                    int h = hist[bin];
                    if (cum + h >= krem) break;
                    cum += h;
                }
                s_prefix = prefix | ((unsigned)bin << shift);
                s_krem = krem - cum;
            }
            __syncthreads();
        }
        unsigned t = s_prefix;   // exact bit pattern of the k-th largest value
        float sum = 0.f; int cnt = 0;
        for (int p = tid; p < NP; p += 1024) {
            unsigned u = __float_as_uint(vals[p]);
            if (u > t) { sum += __uint_as_float(u); cnt++; }
        }
#pragma unroll
        for (int s = 16; s > 0; s >>= 1) {
            sum += __shfl_down_sync(0xFFFFFFFFu, sum, s);
            cnt += __shfl_down_sync(0xFFFFFFFFu, cnt, s);
        }
        __shared__ float rsum[32];
        __shared__ int rcnt[32];
        if (lane == 0) { rsum[tid >> 5] = sum; rcnt[tid >> 5] = cnt; }
        __syncthreads();
        if (tid == 0) {
            float S = 0.f; int Cn = 0;
#pragma unroll
            for (int i = 0; i < 32; i++) { S += rsum[i]; Cn += rcnt[i]; }
            topk = S + (float)(k - Cn) * __uint_as_float(t);
        }
    }

    // publish + last-block finalize
    __shared__ bool s_last;
    if (tid == 0) {
        g_topk[b] = topk;
        __threadfence();
        int t = atomicAdd(&g_ticket, 1);
        s_last = (t == NB - 1);
    }
    __syncthreads();

    if (s_last) {
        float ll = 0.f, cc = 0.f; int np = 0;
        if (tid < NB) {
            ll = g_lossl[tid];
            np = g_npos[tid];
            cc = g_cepos[tid] + g_topk[tid];
        }
#pragma unroll
        for (int s = 16; s > 0; s >>= 1) {
            ll += __shfl_down_sync(0xFFFFFFFFu, ll, s);
            cc += __shfl_down_sync(0xFFFFFFFFu, cc, s);
            np += __shfl_down_sync(0xFFFFFFFFu, np, s);
        }
        __shared__ float sl[2], sc[2];
        __shared__ int sn[2];
        if (tid < NB && lane == 0) { sl[tid >> 5] = ll; sc[tid >> 5] = cc; sn[tid >> 5] = np; }
        __syncthreads();
        if (tid == 0) {
            float L  = sl[0] + sl[1];
            float Cx = sc[0] + sc[1];
            float Nf = (float)(sn[0] + sn[1]);
            out[0] = L / Nf;
            out[1] = Cx / Nf;
        }
    }
}

// ---------------- launch ----------------
extern "C" void kernel_launch(void* const* d_in, const int* in_sizes, int n_in,
                              void* d_out, int out_size) {
    const float* loc_data  = (const float*)d_in[0];
    const float* conf_data = (const float*)d_in[1];
    const float* dbox      = (const float*)d_in[2];
    const float* truths    = (const float*)d_in[3];
    const int*   labels    = (const int*)d_in[4];
    float* out = (float*)d_out;

    k_init<<<1, 1024>>>();

    dim3 g1(NCHUNK, NB);
    k_iou<<<g1, 256>>>(dbox, truths);

    dim3 g2(NTILE, NB);
    k_main<<<g2, 256>>>(conf_data, dbox, truths, labels, loc_data);

    k_topk<<<NB, 1024>>>(out);
}